// round 8
// baseline (speedup 1.0000x reference)
#include <cuda_runtime.h>
#include <math.h>

#define BATCH 512
#define TT    2048
#define INP   32
#define H     256
#define DTC   0.1f
#define EPSC  1e-5f
#define BB    4
#define GRID  (BATCH / BB)   /* 128 blocks */
#define NT    512            /* 2 layer-groups x 256 */

typedef unsigned long long ull;

// Transposed-interleaved weight scratch: layout [k/4][j][k&3] per matrix.
#define WOFF_A0 0
#define WOFF_A1 (1 * H * H)
#define WOFF_R0 (2 * H * H)
#define WOFF_R1 (3 * H * H)
#define WOFF_I1 (4 * H * H)
#define WOFF_SK (5 * H * H)
#define WOFF_I0 (6 * H * H)
__device__ __align__(16) float g_Wt[6 * H * H + INP * H];

// Dynamic smem layout (bytes)
#define SM_CMB0  0        /* 256*3*16 = 12288 */
#define SM_CMB1  12288    /* 12288 */
#define SM_H0Q   24576    /* 2 * 4096 */
#define SM_H1Q   32768    /* 2 * 4096 */
#define SM_HA0   40960    /* 4096 */
#define SM_HA1   45056    /* 4096 */
#define SM_SKP   49152    /* 4096 */
#define SM_XQ    53248    /* 512 */
#define SM_RED0  53760    /* 512 */
#define SM_RED1  54272    /* 512 */
#define SM_STAT0 54784    /* 64 */
#define SM_STAT1 54848    /* 64 */
#define SM_EW1   54912    /* 16 */
#define SMEM_BYTES 55296

__device__ __forceinline__ float sigmoidf_(float v) {
    return 1.0f / (1.0f + expf(-v));
}
__device__ __forceinline__ void ffma2(ull& d, ull a, ull b) {
    asm("fma.rn.f32x2 %0, %1, %2, %0;" : "+l"(d) : "l"(a), "l"(b));
}
__device__ __forceinline__ ull fadd2(ull a, ull b) {
    ull r; asm("add.rn.f32x2 %0, %1, %2;" : "=l"(r) : "l"(a), "l"(b)); return r;
}
__device__ __forceinline__ float hadd2(ull a) {
    float lo, hi; asm("mov.b64 {%0, %1}, %2;" : "=f"(lo), "=f"(hi) : "l"(a));
    return lo + hi;
}
__device__ __forceinline__ void barx(int id) {
    asm volatile("bar.sync %0, %1;" :: "r"(id), "r"(256) : "memory");
}

// Group-local reduction over 8 warps of NV values -> stat[0..NV-1].
template <int NV>
__device__ __forceinline__ void group_reduce(float* vals, int barid, int gt,
                                             float (*red)[16], float* stat) {
    #pragma unroll
    for (int o = 16; o > 0; o >>= 1) {
        #pragma unroll
        for (int i = 0; i < NV; i++)
            vals[i] += __shfl_xor_sync(0xffffffffu, vals[i], o);
    }
    int w = gt >> 5, l = gt & 31;
    if (l == 0) {
        #pragma unroll
        for (int i = 0; i < NV; i++) red[w][i] = vals[i];
    }
    barx(barid);
    if (gt < NV) {
        float a = 0.f;
        #pragma unroll
        for (int w2 = 0; w2 < 8; w2++) a += red[w2][gt];
        stat[gt] = a;
    }
    barx(barid);
}

// Write unit-j row values v[0..3] into pair-interleaved layout:
// buf[p*8 + {0..3}] = (h_2p[0], h_2p+1[0], h_2p[1], h_2p+1[1]); +4 = rows 2,3.
__device__ __forceinline__ void writePair(float* buf, int j, const float* v) {
    float o0 = __shfl_xor_sync(0xffffffffu, v[0], 1);
    float o1 = __shfl_xor_sync(0xffffffffu, v[1], 1);
    float o2 = __shfl_xor_sync(0xffffffffu, v[2], 1);
    float o3 = __shfl_xor_sync(0xffffffffu, v[3], 1);
    int p = j >> 1;
    if ((j & 1) == 0) *(float4*)(buf + p * 8)     = make_float4(v[0], o0, v[1], o1);
    else              *(float4*)(buf + p * 8 + 4) = make_float4(o2, v[2], o3, v[3]);
}

// Dual-column GEMM over NCH 4-k chunks. Weights packed (w_k,w_k+1) pairs from
// scratch (coalesced LDG.128, double-buffered); h from pair-layout smem.
// acc[r] = f32x2 (even-k partial, odd-k partial) for row r.
template <int NCH, bool DUAL>
__device__ __forceinline__ void gemm2(const ulonglong2* __restrict__ wX,
                                      const ulonglong2* __restrict__ wY,
                                      const ulonglong2* __restrict__ hq,
                                      ull* aX, ull* aY) {
    ulonglong2 wx = __ldg(wX), wy;
    if (DUAL) wy = __ldg(wY);
    #pragma unroll 4
    for (int i = 0; i < NCH; i++) {
        ulonglong2 cwx = wx, cwy;
        if (DUAL) cwy = wy;
        if (i + 1 < NCH) {
            wx = __ldg(wX + (i + 1) * 256);
            if (DUAL) wy = __ldg(wY + (i + 1) * 256);
        }
        ulonglong2 h0 = hq[4 * i], h1 = hq[4 * i + 1];
        ulonglong2 h2 = hq[4 * i + 2], h3 = hq[4 * i + 3];
        ffma2(aX[0], h0.x, cwx.x); ffma2(aX[1], h0.y, cwx.x);
        ffma2(aX[2], h1.x, cwx.x); ffma2(aX[3], h1.y, cwx.x);
        ffma2(aX[0], h2.x, cwx.y); ffma2(aX[1], h2.y, cwx.y);
        ffma2(aX[2], h3.x, cwx.y); ffma2(aX[3], h3.y, cwx.y);
        if (DUAL) {
            ffma2(aY[0], h0.x, cwy.x); ffma2(aY[1], h0.y, cwy.x);
            ffma2(aY[2], h1.x, cwy.x); ffma2(aY[3], h1.y, cwy.x);
            ffma2(aY[0], h2.x, cwy.y); ffma2(aY[1], h2.y, cwy.y);
            ffma2(aY[2], h3.x, cwy.y); ffma2(aY[3], h3.y, cwy.y);
        }
    }
}

// Exchange colY partials with partner j^128, return full col-j sums (4 rows).
__device__ __forceinline__ void combine4(ulonglong2* cmbg, int j, int barid,
                                         const ull* aX, const ull* aY, float* res) {
    ulonglong2* slot = cmbg + (j ^ 128) * 3;
    ulonglong2 w0, w1;
    w0.x = aY[0]; w0.y = aY[1]; w1.x = aY[2]; w1.y = aY[3];
    slot[0] = w0; slot[1] = w1;
    barx(barid);
    const ulonglong2* my = cmbg + j * 3;
    ulonglong2 p0 = my[0], p1 = my[1];
    res[0] = hadd2(fadd2(aX[0], p0.x));
    res[1] = hadd2(fadd2(aX[1], p0.y));
    res[2] = hadd2(fadd2(aX[2], p1.x));
    res[3] = hadd2(fadd2(aX[3], p1.y));
}

// ---------------------------------------------------------------------------
// Kernel 0: transpose weights into [k/4][j][k&3] interleaved layout.
// ---------------------------------------------------------------------------
__global__ void transpose_kernel(
    const float* __restrict__ A0, const float* __restrict__ A1,
    const float* __restrict__ R0, const float* __restrict__ R1,
    const float* __restrict__ I1, const float* __restrict__ SK,
    const float* __restrict__ I0)
{
    int idx = blockIdx.x * blockDim.x + threadIdx.x;
    const int BIG = 6 * H * H;
    if (idx < BIG) {
        int m = idx >> 16, rem = idx & 65535;
        int k = rem >> 8, j = rem & 255;
        const float* src = (m == 0) ? A0 : (m == 1) ? A1 : (m == 2) ? R0
                         : (m == 3) ? R1 : (m == 4) ? I1 : SK;
        g_Wt[(m << 16) + (k >> 2) * (H * 4) + j * 4 + (k & 3)] = src[rem];
    } else if (idx < BIG + INP * H) {
        int rem = idx - BIG;
        int k = rem >> 8, j = rem & 255;
        g_Wt[BIG + (k >> 2) * (H * 4) + j * 4 + (k & 3)] = I0[rem];
    }
}

// ---------------------------------------------------------------------------
// Kernel 1: ew0[b,t] = mask * sigmoid([x_t, x_{t-1}] @ Wev0 + bev0)
// ---------------------------------------------------------------------------
__global__ void ew0_kernel(const float* __restrict__ x,
                           const float* __restrict__ Wev0,
                           const float* __restrict__ bev0,
                           float* __restrict__ ew0_out) {
    int idx = blockIdx.x * blockDim.x + threadIdx.x;
    if (idx >= BATCH * TT) return;
    int t = idx & (TT - 1);
    float r = 0.f;
    if (t > 0) {
        const float* xc = x + (size_t)idx * INP;
        const float* xp = xc - INP;
        float s = bev0[0];
        #pragma unroll
        for (int i = 0; i < INP; i++) s += xc[i] * Wev0[i];
        #pragma unroll
        for (int i = 0; i < INP; i++) s += xp[i] * Wev0[INP + i];
        r = sigmoidf_(s);
    }
    ew0_out[idx] = r;
}

// ---------------------------------------------------------------------------
// Kernel 2: persistent recurrence. 512 threads = 2 layer-groups x 256.
// Thread j computes cols {j, j^128} over k-half (j>>7); partner has the other
// half; partials exchanged through smem. Group0 = layer0, group1 = layer1.
// ---------------------------------------------------------------------------
__global__ __launch_bounds__(NT, 1) void liquid_kernel(
    const float* __restrict__ x,
    const float* __restrict__ bin0,  const float* __restrict__ brec0,
    const float* __restrict__ battn0,
    const float* __restrict__ tau0,  const float* __restrict__ gamma0, const float* __restrict__ beta0,
    const float* __restrict__ bin1,  const float* __restrict__ brec1,
    const float* __restrict__ battn1,
    const float* __restrict__ Wev1,  const float* __restrict__ bev1,
    const float* __restrict__ tau1,  const float* __restrict__ gamma1, const float* __restrict__ beta1,
    const float* __restrict__ bskip,
    const float* __restrict__ Wout,  const float* __restrict__ bout,
    float* __restrict__ out,
    const float* __restrict__ ew0_all,
    float* __restrict__ ew1_all)
{
    extern __shared__ __align__(16) char smraw[];

    const int tid  = threadIdx.x;
    const int g    = tid >> 8;        // layer-group
    const int j    = tid & 255;       // unit / group-local tid
    const int s    = j >> 7;          // k-half
    const int row0 = blockIdx.x * BB;
    const int barid = 1 + g;

    ulonglong2* cmb  = (ulonglong2*)(smraw + (g ? SM_CMB1 : SM_CMB0));
    float* h0q0 = (float*)(smraw + SM_H0Q);
    float* h0q1 = (float*)(smraw + SM_H0Q + 4096);
    float* h1q0 = (float*)(smraw + SM_H1Q);
    float* h1q1 = (float*)(smraw + SM_H1Q + 4096);
    float* ha0q = (float*)(smraw + SM_HA0);
    float* ha1q = (float*)(smraw + SM_HA1);
    float* skp  = (float*)(smraw + SM_SKP);
    float* xq   = (float*)(smraw + SM_XQ);
    float (*red)[16] = (float (*)[16])(smraw + (g ? SM_RED1 : SM_RED0));
    float* stat      = (float*)(smraw + (g ? SM_STAT1 : SM_STAT0));
    float* ew1_s     = (float*)(smraw + SM_EW1);

    // ---- per-group constants ----
    float c_battn, c_brec, it, c_g, c_b;
    float c_bin0 = 0.f, c_bin1 = 0.f, wv1a = 0.f, wv1b = 0.f, c_bev1 = 0.f;
    float c_bskip = 0.f, c_wout = 0.f;
    if (g == 0) {
        c_battn = battn0[j]; c_brec = brec0[j];
        it = DTC / fminf(fmaxf(tau0[j], 0.1f), 10.0f);
        c_g = gamma0[j]; c_b = beta0[j];
        c_bin0 = bin0[j]; c_bskip = bskip[j];
        wv1a = Wev1[j]; wv1b = Wev1[H + j]; c_bev1 = bev1[0];
    } else {
        c_battn = battn1[j]; c_brec = brec1[j];
        it = DTC / fminf(fmaxf(tau1[j], 0.1f), 10.0f);
        c_g = gamma1[j]; c_b = beta1[j];
        c_bin1 = bin1[j]; c_wout = Wout[j];
    }
    const float gw = c_g * wv1a;

    float C2 = 0.f, C3 = 0.f;
    if (g == 0) {
        float cc[2] = { gw, c_b * wv1a };
        group_reduce<2>(cc, barid, j, red, stat);
        C2 = stat[0]; C3 = stat[1];
    }

    // Weight bases: matrix base + k-half offset + column (ulonglong2 units).
    const int so = s * 32 * 256;
    const ulonglong2* WB = (const ulonglong2*)(g_Wt + (g ? WOFF_A1 : WOFF_A0)) + so;
    const ulonglong2* WC = (const ulonglong2*)(g_Wt + (g ? WOFF_R1 : WOFF_R0)) + so;
    const ulonglong2* WE = (const ulonglong2*)(g_Wt + (g ? WOFF_I1 : WOFF_SK)) + so;
    const ulonglong2* WI = (const ulonglong2*)(g_Wt + WOFF_I0) + j;
    const int jx = j ^ 128;

    float hown[BB] = {0.f, 0.f, 0.f, 0.f};
    if (g == 0) *(float4*)(h0q0 + j * 4) = make_float4(0.f, 0.f, 0.f, 0.f);
    else        *(float4*)(h1q0 + j * 4) = make_float4(0.f, 0.f, 0.f, 0.f);
    __syncthreads();

    for (int t = 0; t < TT; t++) {
        float* hqcur = (t & 1) ? ((g == 0) ? h0q1 : h1q1) : ((g == 0) ? h0q0 : h1q0);
        float* h0nxt = (t & 1) ? h0q0 : h0q1;
        float* h1nxt = (t & 1) ? h1q0 : h1q1;

        if (g == 0) {
            // ---- A: ew0 + x_t staging ----
            float e0r[BB];
            #pragma unroll
            for (int r = 0; r < BB; r++)
                e0r[r] = ew0_all[(size_t)(row0 + r) * TT + t];
            if (j < INP) {
                float xv[4];
                xv[0] = x[((size_t)(row0 + 0) * TT + t) * INP + j];
                xv[1] = x[((size_t)(row0 + 1) * TT + t) * INP + j];
                xv[2] = x[((size_t)(row0 + 2) * TT + t) * INP + j];
                xv[3] = x[((size_t)(row0 + 3) * TT + t) * INP + j];
                writePair(xq, j, xv);
            }
            barx(1);

            // ---- B: attn0 (split) + in0 (full, own col) ----
            ull aX[4] = {0,0,0,0}, aY[4] = {0,0,0,0}, ia[4] = {0,0,0,0};
            gemm2<32, true>(WB + j, WB + jx,
                            (const ulonglong2*)hqcur + s * 128, aX, aY);
            gemm2<8, false>(WI, WI, (const ulonglong2*)xq, ia, ia);
            float av[4];
            combine4(cmb, j, 1, aX, aY, av);
            float i0t[BB], hv[4];
            #pragma unroll
            for (int r = 0; r < BB; r++) {
                i0t[r] = tanhf(hadd2(ia[r]) + c_bin0);
                hv[r]  = hown[r] * sigmoidf_(av[r] + c_battn);
            }
            writePair(ha0q, j, hv);
            barx(1);

            // ---- C: rec0 ----
            ull rX[4] = {0,0,0,0}, rY[4] = {0,0,0,0};
            gemm2<32, true>(WC + j, WC + jx,
                            (const ulonglong2*)ha0q + s * 128, rX, rY);
            float rv[4];
            combine4(cmb, j, 1, rX, rY, rv);

            // ---- D: cell0 + LN0 + folded ew1 logit ----
            float v0[BB], vals[16];
            #pragma unroll
            for (int r = 0; r < BB; r++) {
                float h = hown[r];
                v0[r] = h + it * (-h + i0t[r] + tanhf(rv[r] + c_brec)) * (1.f + e0r[r]);
                vals[4 * r + 0] = v0[r];
                vals[4 * r + 1] = v0[r] * v0[r];
                vals[4 * r + 2] = v0[r] * gw;
                vals[4 * r + 3] = h * wv1b;
            }
            group_reduce<16>(vals, 1, j, red, stat);

            float h0n[BB];
            #pragma unroll
            for (int r = 0; r < BB; r++) {
                float mu  = stat[4 * r] * (1.f / H);
                float var = stat[4 * r + 1] * (1.f / H) - mu * mu;
                h0n[r] = (v0[r] - mu) * rsqrtf(var + EPSC) * c_g + c_b;
            }
            writePair(h0nxt, j, h0n);
            if (j < BB) {
                int r = j;
                float mu  = stat[4 * r] * (1.f / H);
                float var = stat[4 * r + 1] * (1.f / H) - mu * mu;
                float rs  = rsqrtf(var + EPSC);
                float lg  = rs * (stat[4 * r + 2] - mu * C2) + C3 + stat[4 * r + 3] + c_bev1;
                float e   = (t > 0) ? sigmoidf_(lg) : 0.f;
                ew1_s[r]  = e;
                ew1_all[(size_t)(row0 + r) * TT + t] = e;
            }
            __syncthreads();   // FULL1: h0nxt + ew1_s -> g1

            // ---- E: skip ----
            ull sX[4] = {0,0,0,0}, sY[4] = {0,0,0,0};
            gemm2<32, true>(WE + j, WE + jx,
                            (const ulonglong2*)h0nxt + s * 128, sX, sY);
            float sv[4];
            combine4(cmb, j, 1, sX, sY, sv);
            *(float4*)(skp + j * 4) = make_float4(sv[0] + c_bskip, sv[1] + c_bskip,
                                                  sv[2] + c_bskip, sv[3] + c_bskip);
            __syncthreads();   // FULL2: skp -> g1

            #pragma unroll
            for (int r = 0; r < BB; r++) hown[r] = h0n[r];
        } else {
            // ---- B: attn1 ----
            barx(2);           // orders prev-step h1nxt write -> read
            ull aX[4] = {0,0,0,0}, aY[4] = {0,0,0,0};
            gemm2<32, true>(WB + j, WB + jx,
                            (const ulonglong2*)hqcur + s * 128, aX, aY);
            float av[4];
            combine4(cmb, j, 2, aX, aY, av);
            float hv[4];
            #pragma unroll
            for (int r = 0; r < BB; r++)
                hv[r] = hown[r] * sigmoidf_(av[r] + c_battn);
            writePair(ha1q, j, hv);
            barx(2);

            // ---- C: rec1 ----
            ull rX[4] = {0,0,0,0}, rY[4] = {0,0,0,0};
            gemm2<32, true>(WC + j, WC + jx,
                            (const ulonglong2*)ha1q + s * 128, rX, rY);
            float rv[4];
            combine4(cmb, j, 2, rX, rY, rv);
            float t_rc1[BB];
            #pragma unroll
            for (int r = 0; r < BB; r++) t_rc1[r] = tanhf(rv[r] + c_brec);

            __syncthreads();   // FULL1: wait h0nxt + ew1_s

            // ---- E: in1 ----
            ull iX[4] = {0,0,0,0}, iY[4] = {0,0,0,0};
            gemm2<32, true>(WE + j, WE + jx,
                            (const ulonglong2*)h0nxt + s * 128, iX, iY);
            float iv[4];
            combine4(cmb, j, 2, iX, iY, iv);
            float i1t[BB];
            #pragma unroll
            for (int r = 0; r < BB; r++) i1t[r] = tanhf(iv[r] + c_bin1);

            __syncthreads();   // FULL2: wait skp

            // ---- F: cell1 + LN1 + skip ----
            float4 sk4 = *(const float4*)(skp + j * 4);
            float skv[4] = { sk4.x, sk4.y, sk4.z, sk4.w };
            float ewl[4] = { ew1_s[0], ew1_s[1], ew1_s[2], ew1_s[3] };
            float v1[BB], vf[8];
            #pragma unroll
            for (int r = 0; r < BB; r++) {
                float h = hown[r];
                v1[r] = h + it * (-h + i1t[r] + t_rc1[r]) * (1.f + ewl[r]);
                vf[2 * r]     = v1[r];
                vf[2 * r + 1] = v1[r] * v1[r];
            }
            group_reduce<8>(vf, 2, j, red, stat);
            #pragma unroll
            for (int r = 0; r < BB; r++) {
                float mu  = stat[2 * r] * (1.f / H);
                float var = stat[2 * r + 1] * (1.f / H) - mu * mu;
                hown[r] = (v1[r] - mu) * rsqrtf(var + EPSC) * c_g + c_b + skv[r];
            }
            writePair(h1nxt, j, hown);
            // next step's barx(2) orders these writes
        }
    }

    // ---- Final readout: out[b] = h1 @ Wout + bout (g1) ----
    __syncthreads();
    if (g == 1) {
        float oc[BB];
        #pragma unroll
        for (int r = 0; r < BB; r++) oc[r] = hown[r] * c_wout;
        group_reduce<4>(oc, 2, j, red, stat);
        if (j < BB) out[row0 + j] = stat[j] + bout[0];
    }
}

extern "C" void kernel_launch(void* const* d_in, const int* in_sizes, int n_in,
                              void* d_out, int out_size) {
    const float* x      = (const float*)d_in[0];
    const float* Win0   = (const float*)d_in[1];
    const float* bin0   = (const float*)d_in[2];
    const float* Wrec0  = (const float*)d_in[3];
    const float* brec0  = (const float*)d_in[4];
    const float* Wattn0 = (const float*)d_in[5];
    const float* battn0 = (const float*)d_in[6];
    const float* Wev0   = (const float*)d_in[7];
    const float* bev0   = (const float*)d_in[8];
    const float* tau0   = (const float*)d_in[9];
    const float* gamma0 = (const float*)d_in[10];
    const float* beta0  = (const float*)d_in[11];
    const float* Win1   = (const float*)d_in[12];
    const float* bin1   = (const float*)d_in[13];
    const float* Wrec1  = (const float*)d_in[14];
    const float* brec1  = (const float*)d_in[15];
    const float* Wattn1 = (const float*)d_in[16];
    const float* battn1 = (const float*)d_in[17];
    const float* Wev1   = (const float*)d_in[18];
    const float* bev1   = (const float*)d_in[19];
    const float* tau1   = (const float*)d_in[20];
    const float* gamma1 = (const float*)d_in[21];
    const float* beta1  = (const float*)d_in[22];
    const float* Wskip  = (const float*)d_in[23];
    const float* bskip  = (const float*)d_in[24];
    const float* Wout   = (const float*)d_in[25];
    const float* bout   = (const float*)d_in[26];

    float* out = (float*)d_out;
    float* ew0 = out + BATCH;
    float* ew1 = ew0 + (size_t)BATCH * TT;

    const int TOT = 6 * H * H + INP * H;
    transpose_kernel<<<(TOT + 255) / 256, 256>>>(Wattn0, Wattn1, Wrec0, Wrec1,
                                                 Win1, Wskip, Win0);
    ew0_kernel<<<(BATCH * TT + 255) / 256, 256>>>(x, Wev0, bev0, ew0);

    static int smem_set = 0;
    if (!smem_set) {
        cudaFuncSetAttribute(liquid_kernel,
                             cudaFuncAttributeMaxDynamicSharedMemorySize,
                             SMEM_BYTES);
        smem_set = 1;
    }

    liquid_kernel<<<GRID, NT, SMEM_BYTES>>>(
        x, bin0, brec0, battn0, tau0, gamma0, beta0,
        bin1, brec1, battn1, Wev1, bev1, tau1, gamma1, beta1,
        bskip, Wout, bout,
        out, ew0, ew1);
}

// round 9
// speedup vs baseline: 1.0014x; 1.0014x over previous
#include <cuda_runtime.h>
#include <math.h>

#define BATCH 512
#define TT    2048
#define INP   32
#define H     256
#define DTC   0.1f
#define EPSC  1e-5f
#define BB    4
#define GRID  (BATCH / BB)   /* 128 blocks */
#define NT    512            /* 2 layer-groups x 256 */

typedef unsigned long long ull;

// Transposed-interleaved weight scratch: layout [k/4][j][k&3] per matrix.
#define WOFF_A0 0
#define WOFF_A1 (1 * H * H)
#define WOFF_R0 (2 * H * H)
#define WOFF_R1 (3 * H * H)
#define WOFF_I1 (4 * H * H)
#define WOFF_SK (5 * H * H)
#define WOFF_I0 (6 * H * H)
__device__ __align__(16) float g_Wt[6 * H * H + INP * H];

// Dynamic smem layout (bytes)
#define SM_H0Q   0        /* 2 * 4096 */
#define SM_H1Q   8192     /* 2 * 4096 */
#define SM_HA0   16384    /* 4096 */
#define SM_HA1   20480    /* 4096 */
#define SM_SKP   24576    /* 4096 */
#define SM_XQ    28672    /* 512 */
#define SM_RED0  29184    /* 512 */
#define SM_RED1  29696    /* 512 */
#define SM_STAT0 30208    /* 64 */
#define SM_STAT1 30272    /* 64 */
#define SM_EW1   30336    /* 16 */
#define SMEM_BYTES 30720

__device__ __forceinline__ float sigmoidf_(float v) {
    return 1.0f / (1.0f + expf(-v));
}
__device__ __forceinline__ void ffma2(ull& d, ull a, ull b) {
    asm("fma.rn.f32x2 %0, %1, %2, %0;" : "+l"(d) : "l"(a), "l"(b));
}
__device__ __forceinline__ ull fadd2(ull a, ull b) {
    ull r; asm("add.rn.f32x2 %0, %1, %2;" : "=l"(r) : "l"(a), "l"(b)); return r;
}
__device__ __forceinline__ float hadd2(ull a) {
    float lo, hi; asm("mov.b64 {%0, %1}, %2;" : "=f"(lo), "=f"(hi) : "l"(a));
    return lo + hi;
}
__device__ __forceinline__ void barx(int id) {
    asm volatile("bar.sync %0, %1;" :: "r"(id), "r"(256) : "memory");
}

// Group-local reduction over 8 warps of NV values -> stat[0..NV-1].
template <int NV>
__device__ __forceinline__ void group_reduce(float* vals, int barid, int gt,
                                             float (*red)[16], float* stat) {
    #pragma unroll
    for (int o = 16; o > 0; o >>= 1) {
        #pragma unroll
        for (int i = 0; i < NV; i++)
            vals[i] += __shfl_xor_sync(0xffffffffu, vals[i], o);
    }
    int w = gt >> 5, l = gt & 31;
    if (l == 0) {
        #pragma unroll
        for (int i = 0; i < NV; i++) red[w][i] = vals[i];
    }
    barx(barid);
    if (gt < NV) {
        float a = 0.f;
        #pragma unroll
        for (int w2 = 0; w2 < 8; w2++) a += red[w2][gt];
        stat[gt] = a;
    }
    barx(barid);
}

// Write unit-j row values v[0..3] into pair-interleaved layout:
// buf[p*8 + {0..3}] = (h_2p[0], h_2p+1[0], h_2p[1], h_2p+1[1]); +4 = rows 2,3.
__device__ __forceinline__ void writePair(float* buf, int j, const float* v) {
    float o0 = __shfl_xor_sync(0xffffffffu, v[0], 1);
    float o1 = __shfl_xor_sync(0xffffffffu, v[1], 1);
    float o2 = __shfl_xor_sync(0xffffffffu, v[2], 1);
    float o3 = __shfl_xor_sync(0xffffffffu, v[3], 1);
    int p = j >> 1;
    if ((j & 1) == 0) *(float4*)(buf + p * 8)     = make_float4(v[0], o0, v[1], o1);
    else              *(float4*)(buf + p * 8 + 4) = make_float4(o2, v[2], o3, v[3]);
}

// Dual-column GEMM over NCH 4-k chunks. Weights packed (w_k,w_k+1) pairs from
// scratch (coalesced LDG.128, prefetch distance 2); h from pair-layout smem.
// acc[r] = f32x2 (even-k partial, odd-k partial) for row r.
template <int NCH, bool DUAL>
__device__ __forceinline__ void gemm2(const ulonglong2* __restrict__ wX,
                                      const ulonglong2* __restrict__ wY,
                                      const ulonglong2* __restrict__ hq,
                                      ull* aX, ull* aY) {
    ulonglong2 w0x = __ldg(wX), w1x, w0y, w1y;
    if (NCH > 1) w1x = __ldg(wX + 256);
    if (DUAL) {
        w0y = __ldg(wY);
        if (NCH > 1) w1y = __ldg(wY + 256);
    }
    #pragma unroll 4
    for (int i = 0; i < NCH; i++) {
        ulonglong2 cwx = w0x, cwy;
        if (DUAL) cwy = w0y;
        w0x = w1x;
        if (DUAL) w0y = w1y;
        if (i + 2 < NCH) {
            w1x = __ldg(wX + (i + 2) * 256);
            if (DUAL) w1y = __ldg(wY + (i + 2) * 256);
        }
        ulonglong2 h0 = hq[4 * i], h1 = hq[4 * i + 1];
        ulonglong2 h2 = hq[4 * i + 2], h3 = hq[4 * i + 3];
        ffma2(aX[0], h0.x, cwx.x); ffma2(aX[1], h0.y, cwx.x);
        ffma2(aX[2], h1.x, cwx.x); ffma2(aX[3], h1.y, cwx.x);
        ffma2(aX[0], h2.x, cwx.y); ffma2(aX[1], h2.y, cwx.y);
        ffma2(aX[2], h3.x, cwx.y); ffma2(aX[3], h3.y, cwx.y);
        if (DUAL) {
            ffma2(aY[0], h0.x, cwy.x); ffma2(aY[1], h0.y, cwy.x);
            ffma2(aY[2], h1.x, cwy.x); ffma2(aY[3], h1.y, cwy.x);
            ffma2(aY[0], h2.x, cwy.y); ffma2(aY[1], h2.y, cwy.y);
            ffma2(aY[2], h3.x, cwy.y); ffma2(aY[3], h3.y, cwy.y);
        }
    }
}

// Exchange colY partials with same-warp partner (lane j^16) and finish col-j
// sums for 4 rows. No barrier, no smem: pure warp shuffle.
__device__ __forceinline__ void combineShfl(const ull* aX, const ull* aY, float* res) {
    #pragma unroll
    for (int r = 0; r < 4; r++) {
        ull p = __shfl_xor_sync(0xffffffffu, aY[r], 16);
        res[r] = hadd2(fadd2(aX[r], p));
    }
}

// ---------------------------------------------------------------------------
// Kernel 0: transpose weights into [k/4][j][k&3] interleaved layout.
// ---------------------------------------------------------------------------
__global__ void transpose_kernel(
    const float* __restrict__ A0, const float* __restrict__ A1,
    const float* __restrict__ R0, const float* __restrict__ R1,
    const float* __restrict__ I1, const float* __restrict__ SK,
    const float* __restrict__ I0)
{
    int idx = blockIdx.x * blockDim.x + threadIdx.x;
    const int BIG = 6 * H * H;
    if (idx < BIG) {
        int m = idx >> 16, rem = idx & 65535;
        int k = rem >> 8, j = rem & 255;
        const float* src = (m == 0) ? A0 : (m == 1) ? A1 : (m == 2) ? R0
                         : (m == 3) ? R1 : (m == 4) ? I1 : SK;
        g_Wt[(m << 16) + (k >> 2) * (H * 4) + j * 4 + (k & 3)] = src[rem];
    } else if (idx < BIG + INP * H) {
        int rem = idx - BIG;
        int k = rem >> 8, j = rem & 255;
        g_Wt[BIG + (k >> 2) * (H * 4) + j * 4 + (k & 3)] = I0[rem];
    }
}

// ---------------------------------------------------------------------------
// Kernel 1: ew0[b,t] = mask * sigmoid([x_t, x_{t-1}] @ Wev0 + bev0)
// ---------------------------------------------------------------------------
__global__ void ew0_kernel(const float* __restrict__ x,
                           const float* __restrict__ Wev0,
                           const float* __restrict__ bev0,
                           float* __restrict__ ew0_out) {
    int idx = blockIdx.x * blockDim.x + threadIdx.x;
    if (idx >= BATCH * TT) return;
    int t = idx & (TT - 1);
    float r = 0.f;
    if (t > 0) {
        const float* xc = x + (size_t)idx * INP;
        const float* xp = xc - INP;
        float s = bev0[0];
        #pragma unroll
        for (int i = 0; i < INP; i++) s += xc[i] * Wev0[i];
        #pragma unroll
        for (int i = 0; i < INP; i++) s += xp[i] * Wev0[INP + i];
        r = sigmoidf_(s);
    }
    ew0_out[idx] = r;
}

// ---------------------------------------------------------------------------
// Kernel 2: persistent recurrence. 512 threads = 2 layer-groups x 256.
// Thread j computes cols {j, j^16} over k-half ((j>>4)&1); same-warp partner
// j^16 computes the complementary half; partials combined via shfl (no bar).
// Group0 = layer0, group1 = layer1.
// ---------------------------------------------------------------------------
__global__ __launch_bounds__(NT, 1) void liquid_kernel(
    const float* __restrict__ x,
    const float* __restrict__ bin0,  const float* __restrict__ brec0,
    const float* __restrict__ battn0,
    const float* __restrict__ tau0,  const float* __restrict__ gamma0, const float* __restrict__ beta0,
    const float* __restrict__ bin1,  const float* __restrict__ brec1,
    const float* __restrict__ battn1,
    const float* __restrict__ Wev1,  const float* __restrict__ bev1,
    const float* __restrict__ tau1,  const float* __restrict__ gamma1, const float* __restrict__ beta1,
    const float* __restrict__ bskip,
    const float* __restrict__ Wout,  const float* __restrict__ bout,
    float* __restrict__ out,
    const float* __restrict__ ew0_all,
    float* __restrict__ ew1_all)
{
    extern __shared__ __align__(16) char smraw[];

    const int tid  = threadIdx.x;
    const int g    = tid >> 8;        // layer-group
    const int j    = tid & 255;       // unit / group-local tid
    const int s    = (j >> 4) & 1;    // k-half (partner j^16 in same warp)
    const int row0 = blockIdx.x * BB;
    const int barid = 1 + g;

    float* h0q0 = (float*)(smraw + SM_H0Q);
    float* h0q1 = (float*)(smraw + SM_H0Q + 4096);
    float* h1q0 = (float*)(smraw + SM_H1Q);
    float* h1q1 = (float*)(smraw + SM_H1Q + 4096);
    float* ha0q = (float*)(smraw + SM_HA0);
    float* ha1q = (float*)(smraw + SM_HA1);
    float* skp  = (float*)(smraw + SM_SKP);
    float* xq   = (float*)(smraw + SM_XQ);
    float (*red)[16] = (float (*)[16])(smraw + (g ? SM_RED1 : SM_RED0));
    float* stat      = (float*)(smraw + (g ? SM_STAT1 : SM_STAT0));
    float* ew1_s     = (float*)(smraw + SM_EW1);

    // ---- per-group constants ----
    float c_battn, c_brec, it, c_g, c_b;
    float c_bin0 = 0.f, c_bin1 = 0.f, wv1a = 0.f, wv1b = 0.f, c_bev1 = 0.f;
    float c_bskip = 0.f, c_wout = 0.f;
    if (g == 0) {
        c_battn = battn0[j]; c_brec = brec0[j];
        it = DTC / fminf(fmaxf(tau0[j], 0.1f), 10.0f);
        c_g = gamma0[j]; c_b = beta0[j];
        c_bin0 = bin0[j]; c_bskip = bskip[j];
        wv1a = Wev1[j]; wv1b = Wev1[H + j]; c_bev1 = bev1[0];
    } else {
        c_battn = battn1[j]; c_brec = brec1[j];
        it = DTC / fminf(fmaxf(tau1[j], 0.1f), 10.0f);
        c_g = gamma1[j]; c_b = beta1[j];
        c_bin1 = bin1[j]; c_wout = Wout[j];
    }
    const float gw = c_g * wv1a;

    float C2 = 0.f, C3 = 0.f;
    if (g == 0) {
        float cc[2] = { gw, c_b * wv1a };
        group_reduce<2>(cc, barid, j, red, stat);
        C2 = stat[0]; C3 = stat[1];
    }

    // Weight bases: matrix base + k-half offset (ulonglong2 units).
    const int so = s * 32 * 256;
    const ulonglong2* WB = (const ulonglong2*)(g_Wt + (g ? WOFF_A1 : WOFF_A0)) + so;
    const ulonglong2* WC = (const ulonglong2*)(g_Wt + (g ? WOFF_R1 : WOFF_R0)) + so;
    const ulonglong2* WE = (const ulonglong2*)(g_Wt + (g ? WOFF_I1 : WOFF_SK)) + so;
    const ulonglong2* WI = (const ulonglong2*)(g_Wt + WOFF_I0) + j;
    const int jx = j ^ 16;

    float hown[BB] = {0.f, 0.f, 0.f, 0.f};
    if (g == 0) *(float4*)(h0q0 + j * 4) = make_float4(0.f, 0.f, 0.f, 0.f);
    else        *(float4*)(h1q0 + j * 4) = make_float4(0.f, 0.f, 0.f, 0.f);
    __syncthreads();

    for (int t = 0; t < TT; t++) {
        float* hqcur = (t & 1) ? ((g == 0) ? h0q1 : h1q1) : ((g == 0) ? h0q0 : h1q0);
        float* h0nxt = (t & 1) ? h0q0 : h0q1;
        float* h1nxt = (t & 1) ? h1q0 : h1q1;

        if (g == 0) {
            // ---- A: ew0 + x_t staging ----
            float e0r[BB];
            #pragma unroll
            for (int r = 0; r < BB; r++)
                e0r[r] = ew0_all[(size_t)(row0 + r) * TT + t];
            if (j < INP) {
                float xv[4];
                xv[0] = x[((size_t)(row0 + 0) * TT + t) * INP + j];
                xv[1] = x[((size_t)(row0 + 1) * TT + t) * INP + j];
                xv[2] = x[((size_t)(row0 + 2) * TT + t) * INP + j];
                xv[3] = x[((size_t)(row0 + 3) * TT + t) * INP + j];
                writePair(xq, j, xv);
            }
            barx(1);

            // ---- B: attn0 (split, shfl-combined) + in0 (full, own col) ----
            ull aX[4] = {0,0,0,0}, aY[4] = {0,0,0,0}, ia[4] = {0,0,0,0};
            gemm2<32, true>(WB + j, WB + jx,
                            (const ulonglong2*)hqcur + s * 128, aX, aY);
            gemm2<8, false>(WI, WI, (const ulonglong2*)xq, ia, ia);
            float av[4];
            combineShfl(aX, aY, av);
            float i0t[BB], hv[4];
            #pragma unroll
            for (int r = 0; r < BB; r++) {
                i0t[r] = tanhf(hadd2(ia[r]) + c_bin0);
                hv[r]  = hown[r] * sigmoidf_(av[r] + c_battn);
            }
            writePair(ha0q, j, hv);
            barx(1);

            // ---- C: rec0 ----
            ull rX[4] = {0,0,0,0}, rY[4] = {0,0,0,0};
            gemm2<32, true>(WC + j, WC + jx,
                            (const ulonglong2*)ha0q + s * 128, rX, rY);
            float rv[4];
            combineShfl(rX, rY, rv);

            // ---- D: cell0 + LN0 + folded ew1 logit ----
            float v0[BB], vals[16];
            #pragma unroll
            for (int r = 0; r < BB; r++) {
                float h = hown[r];
                v0[r] = h + it * (-h + i0t[r] + tanhf(rv[r] + c_brec)) * (1.f + e0r[r]);
                vals[4 * r + 0] = v0[r];
                vals[4 * r + 1] = v0[r] * v0[r];
                vals[4 * r + 2] = v0[r] * gw;
                vals[4 * r + 3] = h * wv1b;
            }
            group_reduce<16>(vals, 1, j, red, stat);

            float h0n[BB];
            #pragma unroll
            for (int r = 0; r < BB; r++) {
                float mu  = stat[4 * r] * (1.f / H);
                float var = stat[4 * r + 1] * (1.f / H) - mu * mu;
                h0n[r] = (v0[r] - mu) * rsqrtf(var + EPSC) * c_g + c_b;
            }
            writePair(h0nxt, j, h0n);
            if (j < BB) {
                int r = j;
                float mu  = stat[4 * r] * (1.f / H);
                float var = stat[4 * r + 1] * (1.f / H) - mu * mu;
                float rs  = rsqrtf(var + EPSC);
                float lg  = rs * (stat[4 * r + 2] - mu * C2) + C3 + stat[4 * r + 3] + c_bev1;
                float e   = (t > 0) ? sigmoidf_(lg) : 0.f;
                ew1_s[r]  = e;
                ew1_all[(size_t)(row0 + r) * TT + t] = e;
            }
            __syncthreads();   // FULL1: h0nxt + ew1_s -> g1

            // ---- E: skip ----
            ull sX[4] = {0,0,0,0}, sY[4] = {0,0,0,0};
            gemm2<32, true>(WE + j, WE + jx,
                            (const ulonglong2*)h0nxt + s * 128, sX, sY);
            float sv[4];
            combineShfl(sX, sY, sv);
            *(float4*)(skp + j * 4) = make_float4(sv[0] + c_bskip, sv[1] + c_bskip,
                                                  sv[2] + c_bskip, sv[3] + c_bskip);
            __syncthreads();   // FULL2: skp -> g1

            #pragma unroll
            for (int r = 0; r < BB; r++) hown[r] = h0n[r];
        } else {
            // ---- B: attn1 ----
            barx(2);           // orders prev-step h1nxt write -> read
            ull aX[4] = {0,0,0,0}, aY[4] = {0,0,0,0};
            gemm2<32, true>(WB + j, WB + jx,
                            (const ulonglong2*)hqcur + s * 128, aX, aY);
            float av[4];
            combineShfl(aX, aY, av);
            float hv[4];
            #pragma unroll
            for (int r = 0; r < BB; r++)
                hv[r] = hown[r] * sigmoidf_(av[r] + c_battn);
            writePair(ha1q, j, hv);
            barx(2);

            // ---- C: rec1 ----
            ull rX[4] = {0,0,0,0}, rY[4] = {0,0,0,0};
            gemm2<32, true>(WC + j, WC + jx,
                            (const ulonglong2*)ha1q + s * 128, rX, rY);
            float rv[4];
            combineShfl(rX, rY, rv);
            float t_rc1[BB];
            #pragma unroll
            for (int r = 0; r < BB; r++) t_rc1[r] = tanhf(rv[r] + c_brec);

            __syncthreads();   // FULL1: wait h0nxt + ew1_s

            // ---- E: in1 ----
            ull iX[4] = {0,0,0,0}, iY[4] = {0,0,0,0};
            gemm2<32, true>(WE + j, WE + jx,
                            (const ulonglong2*)h0nxt + s * 128, iX, iY);
            float iv[4];
            combineShfl(iX, iY, iv);
            float i1t[BB];
            #pragma unroll
            for (int r = 0; r < BB; r++) i1t[r] = tanhf(iv[r] + c_bin1);

            __syncthreads();   // FULL2: wait skp

            // ---- F: cell1 + LN1 + skip ----
            float4 sk4 = *(const float4*)(skp + j * 4);
            float skv[4] = { sk4.x, sk4.y, sk4.z, sk4.w };
            float ewl[4] = { ew1_s[0], ew1_s[1], ew1_s[2], ew1_s[3] };
            float v1[BB], vf[8];
            #pragma unroll
            for (int r = 0; r < BB; r++) {
                float h = hown[r];
                v1[r] = h + it * (-h + i1t[r] + t_rc1[r]) * (1.f + ewl[r]);
                vf[2 * r]     = v1[r];
                vf[2 * r + 1] = v1[r] * v1[r];
            }
            group_reduce<8>(vf, 2, j, red, stat);
            #pragma unroll
            for (int r = 0; r < BB; r++) {
                float mu  = stat[2 * r] * (1.f / H);
                float var = stat[2 * r + 1] * (1.f / H) - mu * mu;
                hown[r] = (v1[r] - mu) * rsqrtf(var + EPSC) * c_g + c_b + skv[r];
            }
            writePair(h1nxt, j, hown);
            // next step's barx(2) orders these writes
        }
    }

    // ---- Final readout: out[b] = h1 @ Wout + bout (g1) ----
    __syncthreads();
    if (g == 1) {
        float oc[BB];
        #pragma unroll
        for (int r = 0; r < BB; r++) oc[r] = hown[r] * c_wout;
        group_reduce<4>(oc, 2, j, red, stat);
        if (j < BB) out[row0 + j] = stat[j] + bout[0];
    }
}

extern "C" void kernel_launch(void* const* d_in, const int* in_sizes, int n_in,
                              void* d_out, int out_size) {
    const float* x      = (const float*)d_in[0];
    const float* Win0   = (const float*)d_in[1];
    const float* bin0   = (const float*)d_in[2];
    const float* Wrec0  = (const float*)d_in[3];
    const float* brec0  = (const float*)d_in[4];
    const float* Wattn0 = (const float*)d_in[5];
    const float* battn0 = (const float*)d_in[6];
    const float* Wev0   = (const float*)d_in[7];
    const float* bev0   = (const float*)d_in[8];
    const float* tau0   = (const float*)d_in[9];
    const float* gamma0 = (const float*)d_in[10];
    const float* beta0  = (const float*)d_in[11];
    const float* Win1   = (const float*)d_in[12];
    const float* bin1   = (const float*)d_in[13];
    const float* Wrec1  = (const float*)d_in[14];
    const float* brec1  = (const float*)d_in[15];
    const float* Wattn1 = (const float*)d_in[16];
    const float* battn1 = (const float*)d_in[17];
    const float* Wev1   = (const float*)d_in[18];
    const float* bev1   = (const float*)d_in[19];
    const float* tau1   = (const float*)d_in[20];
    const float* gamma1 = (const float*)d_in[21];
    const float* beta1  = (const float*)d_in[22];
    const float* Wskip  = (const float*)d_in[23];
    const float* bskip  = (const float*)d_in[24];
    const float* Wout   = (const float*)d_in[25];
    const float* bout   = (const float*)d_in[26];

    float* out = (float*)d_out;
    float* ew0 = out + BATCH;
    float* ew1 = ew0 + (size_t)BATCH * TT;

    const int TOT = 6 * H * H + INP * H;
    transpose_kernel<<<(TOT + 255) / 256, 256>>>(Wattn0, Wattn1, Wrec0, Wrec1,
                                                 Win1, Wskip, Win0);
    ew0_kernel<<<(BATCH * TT + 255) / 256, 256>>>(x, Wev0, bev0, ew0);

    static int smem_set = 0;
    if (!smem_set) {
        cudaFuncSetAttribute(liquid_kernel,
                             cudaFuncAttributeMaxDynamicSharedMemorySize,
                             SMEM_BYTES);
        smem_set = 1;
    }

    liquid_kernel<<<GRID, NT, SMEM_BYTES>>>(
        x, bin0, brec0, battn0, tau0, gamma0, beta0,
        bin1, brec1, battn1, Wev1, bev1, tau1, gamma1, beta1,
        bskip, Wout, bout,
        out, ew0, ew1);
}